// round 10
// baseline (speedup 1.0000x reference)
#include <cuda_runtime.h>
#include <cuda_bf16.h>
#include <cstdint>

// Problem constants
#define NN   4096
#define DD   128
#define HH   8
#define ALPHA 0.2f
#define LN_EPS 1e-5f
#define NJC  256           // 256 k-chunks of 16 j

typedef unsigned long long u64;

// ---------------- scratch (device globals; no allocation allowed) ----------------
// Wh^T in m16n8k16 B-fragment order, hi/lo interleaved per uint4, COALESCED:
// bf16 elem idx = ((((h*NJC + jc)*16 + dt)*32 + lane)*4 + comp)*2 + half
//   comp: 0=b0hi 1=b1hi 2=b0lo 3=b1lo ; b-reg = kk>>3 ; half = kk&1
//   lane = (d&7)*4 + ((kk&7)>>1) ; dt = d>>3 ; kk = j&15 ; jc = j>>4
__device__ __nv_bfloat16 g_whB[(size_t)HH * NJC * 16 * 32 * 8];   // 16.8 MB
__device__ float4   g_fq [HH * NN];                 // (f1, e^f1, e^{a f1}, 0)
__device__ float4   g_fk [HH * NN];                 // (f2, e^f2, e^{a f2}, 0)
__device__ float    g_cat[(size_t)NN * (HH * DD)];  // [n][h*128+d], 16 MB
__device__ unsigned g_adjbits[NN * (NN / 32)];      // bit-packed adj, 2 MB

// ---------------- helpers ----------------
__device__ __forceinline__ u64 pack2(float x, float y) {
    u64 r; asm("mov.b64 %0, {%1, %2};" : "=l"(r) : "f"(x), "f"(y)); return r;
}
__device__ __forceinline__ float2 unpack2(u64 v) {
    float2 r; asm("mov.b64 {%0, %1}, %2;" : "=f"(r.x), "=f"(r.y) : "l"(v)); return r;
}
__device__ __forceinline__ u64 ffma2(u64 a, u64 b, u64 c) {
    u64 d; asm("fma.rn.f32x2 %0, %1, %2, %3;" : "=l"(d) : "l"(a), "l"(b), "l"(c)); return d;
}
__device__ __forceinline__ float elu1(float x) { return x > 0.f ? x : expm1f(x); }
__device__ __forceinline__ uint32_t bf2_bits(__nv_bfloat162 v) {
    return *reinterpret_cast<uint32_t*>(&v);
}

// m16n8k16 bf16 mma: D(f32) += A(bf16,row) * B(bf16,col)
__device__ __forceinline__ void mma_bf16(float c[4],
                                         uint32_t a0, uint32_t a1, uint32_t a2, uint32_t a3,
                                         uint32_t b0, uint32_t b1) {
    asm volatile(
        "mma.sync.aligned.m16n8k16.row.col.f32.bf16.bf16.f32 "
        "{%0,%1,%2,%3}, {%4,%5,%6,%7}, {%8,%9}, {%0,%1,%2,%3};"
        : "+f"(c[0]), "+f"(c[1]), "+f"(c[2]), "+f"(c[3])
        : "r"(a0), "r"(a1), "r"(a2), "r"(a3), "r"(b0), "r"(b1));
}

// =================================================================
// Kernel 0: bit-pack adjacency. One warp per 32 columns.
// =================================================================
__global__ void pack_kernel(const int* __restrict__ adj) {
    int w    = blockIdx.x * 8 + (threadIdx.x >> 5);
    int lane = threadIdx.x & 31;
    int av = adj[(size_t)w * 32 + lane];
    unsigned m = __ballot_sync(0xffffffffu, av > 0);
    if (lane == 0) g_adjbits[w] = m;
}

// =================================================================
// Kernel 1: Wh = nodes @ W[h]; writes B-fragments + f1/f2 exp factors
// grid (64, 8), block 256. 64-node tile per CTA.
// =================================================================
__global__ void wh_kernel(const float* __restrict__ nodes, const float* __restrict__ W,
                          const float* __restrict__ a1, const float* __restrict__ a2) {
    __shared__ float ns[64][DD];
    const int h  = blockIdx.y;
    const int nb = blockIdx.x * 64;
    const int tid = threadIdx.x;

#pragma unroll
    for (int i = 0; i < 8; i++) {
        int f  = tid + 256 * i;
        int r  = f >> 5, c4 = f & 31;
        *(float4*)&ns[r][c4 * 4] = *(const float4*)&nodes[(size_t)(nb + r) * DD + c4 * 4];
    }
    __syncthreads();

    const int dg = tid & 31;   // lane: dims dg*4 .. dg*4+3
    const int ng = tid >> 5;   // warp: nodes ng*8 .. ng*8+7
    const float* Wb = W + (size_t)h * DD * DD;

    u64 acc[8][2];
#pragma unroll
    for (int n = 0; n < 8; n++) { acc[n][0] = 0ULL; acc[n][1] = 0ULL; }

#pragma unroll 4
    for (int k = 0; k < DD; k++) {
        float4 w4 = __ldg((const float4*)&Wb[k * DD + dg * 4]);
        u64 wxy = pack2(w4.x, w4.y);
        u64 wzw = pack2(w4.z, w4.w);
#pragma unroll
        for (int n = 0; n < 8; n++) {
            float s = ns[ng * 8 + n][k];
            u64 ss = pack2(s, s);
            acc[n][0] = ffma2(ss, wxy, acc[n][0]);
            acc[n][1] = ffma2(ss, wzw, acc[n][1]);
        }
    }

    float4 wh4[8];
#pragma unroll
    for (int n = 0; n < 8; n++) {
        float2 a = unpack2(acc[n][0]);
        float2 b = unpack2(acc[n][1]);
        wh4[n] = make_float4(a.x, a.y, b.x, b.y);
    }

    // ---- f1/f2 + exp factors ----
    float4 A1 = __ldg((const float4*)&a1[h * DD + dg * 4]);
    float4 A2 = __ldg((const float4*)&a2[h * DD + dg * 4]);
    float s1[8], s2[8];
#pragma unroll
    for (int n = 0; n < 8; n++) {
        s1[n] = wh4[n].x * A1.x + wh4[n].y * A1.y + wh4[n].z * A1.z + wh4[n].w * A1.w;
        s2[n] = wh4[n].x * A2.x + wh4[n].y * A2.y + wh4[n].z * A2.z + wh4[n].w * A2.w;
    }
#pragma unroll
    for (int o = 16; o > 0; o >>= 1) {
#pragma unroll
        for (int n = 0; n < 8; n++) {
            s1[n] += __shfl_xor_sync(0xffffffffu, s1[n], o);
            s2[n] += __shfl_xor_sync(0xffffffffu, s2[n], o);
        }
    }
    if (dg < 8) {
        float v1 = s1[0], v2 = s2[0];
#pragma unroll
        for (int n = 1; n < 8; n++)
            if (dg == n) { v1 = s1[n]; v2 = s2[n]; }
        int node = nb + ng * 8 + dg;
        g_fq[h * NN + node] = make_float4(v1, expf(v1), expf(ALPHA * v1), 0.f);
        g_fk[h * NN + node] = make_float4(v2, expf(v2), expf(ALPHA * v2), 0.f);
    }

    // ---- bf16 hi/lo B-fragment write (coalesced [jc][dt][lane] layout) ----
#pragma unroll
    for (int n = 0; n < 8; n++) {
        int j  = nb + ng * 8 + n;
        int jc = j >> 4, kk = j & 15;
        int comp = kk >> 3;          // which b-reg (hi slot; +2 for lo)
        int half = kk & 1;
        int lk   = (kk & 7) >> 1;
        size_t cb = ((size_t)(h * NJC + jc)) * 16;
        float vals[4] = {wh4[n].x, wh4[n].y, wh4[n].z, wh4[n].w};
#pragma unroll
        for (int q = 0; q < 4; q++) {
            int d = dg * 4 + q;
            int dt = d >> 3;
            int lane2 = (d & 7) * 4 + lk;
            size_t ei = (((cb + dt) * 32 + lane2) * 4 + comp) * 2 + half;
            float v = vals[q];
            __nv_bfloat16 hv = __float2bfloat16(v);
            g_whB[ei]     = hv;                                        // hi (comp)
            g_whB[ei + 4] = __float2bfloat16(v - __bfloat162float(hv)); // lo (comp+2)
        }
    }
}

// =================================================================
// Kernel 2: attention, operand-flipped, barrier-free, SW-pipelined.
// grid (32, 8): 128-query tile per CTA for head h. block 256.
// Warp wid owns q in [qbase + wid*16, +16); all 128 d via 16 n8 tiles.
// Pipeline: rotating 4-deep B batches with cross-iteration prefetch;
// next-chunk scores computed mid-stream between MMA batches.
// =================================================================
__global__ void __launch_bounds__(256, 2) attn_kernel() {
    const int h     = blockIdx.y;
    const int qbase = blockIdx.x * 128;
    const int tid   = threadIdx.x;
    const int wid   = tid >> 5;
    const int lane  = tid & 31;
    const int r4  = lane >> 2;
    const int c42 = (lane & 3) * 2;

    const int q_lo = qbase + wid * 16 + r4;
    const int q_hi = q_lo + 8;

    const float4 fqlo = __ldg(&g_fq[h * NN + q_lo]);
    const float4 fqhi = __ldg(&g_fq[h * NN + q_hi]);

    float acc[16][4];
#pragma unroll
    for (int dt = 0; dt < 16; dt++)
#pragma unroll
        for (int i = 0; i < 4; i++) acc[dt][i] = 0.f;
    float llo = 0.f, lhi = 0.f;

    const float4*   fkb = g_fk + h * NN;
    const unsigned* abl = g_adjbits + (size_t)q_lo * (NN / 32);
    const unsigned* abh = g_adjbits + (size_t)q_hi * (NN / 32);
    const uint4*    Bb  = (const uint4*)g_whB + (size_t)h * NJC * 512 + lane;

#define PVAL(FQ, KV, BIT, W) \
    ({ float _t = (FQ).x + (KV).x; \
       float _p = (_t >= 0.f) ? (FQ).y * (KV).y : (FQ).z * (KV).z; \
       (((W) >> (BIT)) & 1u) ? _p : 0.f; })

    // compute scores for chunk JN into AH[4]/AL[4] (A-frag layout), add to llo/lhi
#define SCORE(JN, AH, AL) do {                                                   \
    int _jn = (JN);                                                              \
    unsigned _wl = __ldg(&abl[_jn >> 1]);                                        \
    unsigned _wh = __ldg(&abh[_jn >> 1]);                                        \
    const int _j0 = _jn * 16 + c42;                                              \
    const int _sh = ((_jn & 1) << 4) + c42;                                      \
    float4 _k0 = __ldg(&fkb[_j0]);                                               \
    float4 _k1 = __ldg(&fkb[_j0 + 1]);                                           \
    float4 _k2 = __ldg(&fkb[_j0 + 8]);                                           \
    float4 _k3 = __ldg(&fkb[_j0 + 9]);                                           \
    float pl0 = PVAL(fqlo, _k0, _sh,     _wl);                                   \
    float pl1 = PVAL(fqlo, _k1, _sh + 1, _wl);                                   \
    float pl2 = PVAL(fqlo, _k2, _sh + 8, _wl);                                   \
    float pl3 = PVAL(fqlo, _k3, _sh + 9, _wl);                                   \
    float ph0 = PVAL(fqhi, _k0, _sh,     _wh);                                   \
    float ph1 = PVAL(fqhi, _k1, _sh + 1, _wh);                                   \
    float ph2 = PVAL(fqhi, _k2, _sh + 8, _wh);                                   \
    float ph3 = PVAL(fqhi, _k3, _sh + 9, _wh);                                   \
    llo += (pl0 + pl1) + (pl2 + pl3);                                            \
    lhi += (ph0 + ph1) + (ph2 + ph3);                                            \
    __nv_bfloat162 hA0 = __floats2bfloat162_rn(pl0, pl1);                        \
    __nv_bfloat162 hA1 = __floats2bfloat162_rn(ph0, ph1);                        \
    __nv_bfloat162 hA2 = __floats2bfloat162_rn(pl2, pl3);                        \
    __nv_bfloat162 hA3 = __floats2bfloat162_rn(ph2, ph3);                        \
    __nv_bfloat162 lA0 = __floats2bfloat162_rn(pl0 - __low2float(hA0), pl1 - __high2float(hA0)); \
    __nv_bfloat162 lA1 = __floats2bfloat162_rn(ph0 - __low2float(hA1), ph1 - __high2float(hA1)); \
    __nv_bfloat162 lA2 = __floats2bfloat162_rn(pl2 - __low2float(hA2), pl3 - __high2float(hA2)); \
    __nv_bfloat162 lA3 = __floats2bfloat162_rn(ph2 - __low2float(hA3), ph3 - __high2float(hA3)); \
    AH[0] = bf2_bits(hA0); AH[1] = bf2_bits(hA1); AH[2] = bf2_bits(hA2); AH[3] = bf2_bits(hA3); \
    AL[0] = bf2_bits(lA0); AL[1] = bf2_bits(lA1); AL[2] = bf2_bits(lA2); AL[3] = bf2_bits(lA3); \
} while (0)

    // 3-pass MMA on one dt with batch reg B
#define MMA3(DT, B) do {                                                         \
    mma_bf16(acc[DT], ah[0], ah[1], ah[2], ah[3], (B).x, (B).y);                 \
    mma_bf16(acc[DT], al[0], al[1], al[2], al[3], (B).x, (B).y);                 \
    mma_bf16(acc[DT], ah[0], ah[1], ah[2], ah[3], (B).z, (B).w);                 \
} while (0)

    uint32_t ah[4], al[4], ahn[4], aln[4];
    uint4 b0[4], b1[4];

    // preamble: scores for jc=0, B batch dt0-3 of jc=0
    SCORE(0, ah, al);
    {
        const uint4* Bp = Bb;
#pragma unroll
        for (int t = 0; t < 4; t++) b0[t] = __ldg(&Bp[t * 32]);
    }

#pragma unroll 1
    for (int jc = 0; jc < NJC; jc++) {
        const uint4* Bp  = Bb + (size_t)jc * 512;
        const uint4* Bpn = Bb + (size_t)((jc + 1) & (NJC - 1)) * 512;

        // batch A: prefetch dt4-7, MMA dt0-3
#pragma unroll
        for (int t = 0; t < 4; t++) b1[t] = __ldg(&Bp[(t + 4) * 32]);
#pragma unroll
        for (int t = 0; t < 4; t++) MMA3(t, b0[t]);

        // batch B: prefetch dt8-11, then next-chunk scores, MMA dt4-7
#pragma unroll
        for (int t = 0; t < 4; t++) b0[t] = __ldg(&Bp[(t + 8) * 32]);
        if (jc + 1 < NJC) SCORE(jc + 1, ahn, aln);
#pragma unroll
        for (int t = 0; t < 4; t++) MMA3(t + 4, b1[t]);

        // batch C: prefetch dt12-15, MMA dt8-11
#pragma unroll
        for (int t = 0; t < 4; t++) b1[t] = __ldg(&Bp[(t + 12) * 32]);
#pragma unroll
        for (int t = 0; t < 4; t++) MMA3(t + 8, b0[t]);

        // batch D: cross-iteration prefetch dt0-3 of jc+1, MMA dt12-15
#pragma unroll
        for (int t = 0; t < 4; t++) b0[t] = __ldg(&Bpn[t * 32]);
#pragma unroll
        for (int t = 0; t < 4; t++) MMA3(t + 12, b1[t]);

        // rotate score double-buffer
#pragma unroll
        for (int t = 0; t < 4; t++) { ah[t] = ahn[t]; al[t] = aln[t]; }
    }
#undef PVAL
#undef SCORE
#undef MMA3

    // softmax denominators: lanes sharing r4 (c4=0..3) cover all j
    llo += __shfl_xor_sync(0xffffffffu, llo, 1);
    llo += __shfl_xor_sync(0xffffffffu, llo, 2);
    lhi += __shfl_xor_sync(0xffffffffu, lhi, 1);
    lhi += __shfl_xor_sync(0xffffffffu, lhi, 2);
    const float inv_lo = 1.f / llo;
    const float inv_hi = 1.f / lhi;

    // normalize + ELU + write concat layout [q][h*128+d]
    float* rowl = g_cat + (size_t)q_lo * (HH * DD) + h * DD;
    float* rowh = g_cat + (size_t)q_hi * (HH * DD) + h * DD;
#pragma unroll
    for (int dt = 0; dt < 16; dt++) {
        int d0 = dt * 8 + c42;
        *(float2*)&rowl[d0] = make_float2(elu1(acc[dt][0] * inv_lo), elu1(acc[dt][1] * inv_lo));
        *(float2*)&rowh[d0] = make_float2(elu1(acc[dt][2] * inv_hi), elu1(acc[dt][3] * inv_hi));
    }
}

// =================================================================
// Kernel 3: x = elu(cat @ W1 + b1); out = LN(nodes + x)
// grid 512 (8 nodes/CTA), block 256 (split-k halves)
// =================================================================
__global__ void out_kernel(const float* __restrict__ nodes,
                           const float* __restrict__ W1,
                           const float* __restrict__ b1,
                           const float* __restrict__ gamma,
                           const float* __restrict__ beta,
                           float* __restrict__ out) {
    __shared__ float cs[8][1024];    // 32 KB
    __shared__ float part[8][DD];    //  4 KB
    __shared__ float rbuf[8][DD];    //  4 KB

    const int nb  = blockIdx.x * 8;
    const int tid = threadIdx.x;
    const int kh  = tid >> 7;        // which k-half
    const int col = tid & 127;

#pragma unroll
    for (int i = 0; i < 8; i++) {
        int f = tid + 256 * i;
        int r = f >> 8, c4 = f & 255;
        *(float4*)&cs[r][c4 * 4] = *(const float4*)&g_cat[(size_t)(nb + r) * 1024 + c4 * 4];
    }
    __syncthreads();

    u64 acc2[8];
#pragma unroll
    for (int n = 0; n < 8; n++) acc2[n] = 0ULL;

    const int kbeg = kh * 512;
    for (int k = kbeg; k < kbeg + 512; k += 4) {
        float w0  = __ldg(&W1[(size_t)(k + 0) * DD + col]);
        float w1v = __ldg(&W1[(size_t)(k + 1) * DD + col]);
        float w2  = __ldg(&W1[(size_t)(k + 2) * DD + col]);
        float w3  = __ldg(&W1[(size_t)(k + 3) * DD + col]);
        u64 ww01 = pack2(w0, w1v);
        u64 ww23 = pack2(w2, w3);
#pragma unroll
        for (int n = 0; n < 8; n++) {
            float4 c = *(float4*)&cs[n][k];
            acc2[n] = ffma2(pack2(c.x, c.y), ww01, acc2[n]);
            acc2[n] = ffma2(pack2(c.z, c.w), ww23, acc2[n]);
        }
    }

    float acc[8];
#pragma unroll
    for (int n = 0; n < 8; n++) {
        float2 t = unpack2(acc2[n]);
        acc[n] = t.x + t.y;
    }

    if (kh == 1) {
#pragma unroll
        for (int n = 0; n < 8; n++) part[n][col] = acc[n];
    }
    __syncthreads();
    if (kh == 0) {
        float bb = __ldg(&b1[col]);
#pragma unroll
        for (int n = 0; n < 8; n++) {
            float x = elu1(acc[n] + part[n][col] + bb);
            rbuf[n][col] = nodes[(size_t)(nb + n) * DD + col] + x;
        }
    }
    __syncthreads();

    const int w    = tid >> 5;
    const int lane = tid & 31;
    float4 G = __ldg((const float4*)&gamma[lane * 4]);
    float4 B = __ldg((const float4*)&beta[lane * 4]);
    {
        float4 r = *(float4*)&rbuf[w][lane * 4];
        float s  = r.x + r.y + r.z + r.w;
        float ss = r.x * r.x + r.y * r.y + r.z * r.z + r.w * r.w;
#pragma unroll
        for (int o = 16; o > 0; o >>= 1) {
            s  += __shfl_xor_sync(0xffffffffu, s, o);
            ss += __shfl_xor_sync(0xffffffffu, ss, o);
        }
        float mu   = s * (1.f / DD);
        float var  = ss * (1.f / DD) - mu * mu;
        float rstd = rsqrtf(var + LN_EPS);
        float4 o4;
        o4.x = (r.x - mu) * rstd * G.x + B.x;
        o4.y = (r.y - mu) * rstd * G.y + B.y;
        o4.z = (r.z - mu) * rstd * G.z + B.z;
        o4.w = (r.w - mu) * rstd * G.w + B.w;
        *(float4*)&out[(size_t)(nb + w) * DD + lane * 4] = o4;
    }
}

// =================================================================
extern "C" void kernel_launch(void* const* d_in, const int* in_sizes, int n_in,
                              void* d_out, int out_size) {
    const float* nodes = (const float*)d_in[0];
    const int*   adj   = (const int*)  d_in[1];
    const float* W     = (const float*)d_in[2];
    const float* a1    = (const float*)d_in[3];
    const float* a2    = (const float*)d_in[4];
    const float* W1    = (const float*)d_in[5];
    const float* b1    = (const float*)d_in[6];
    const float* gamma = (const float*)d_in[7];
    const float* beta  = (const float*)d_in[8];
    float* out = (float*)d_out;

    pack_kernel<<<NN * (NN / 32) / 8, 256>>>(adj);
    wh_kernel  <<<dim3(NN / 64, HH), 256>>>(nodes, W, a1, a2);
    attn_kernel<<<dim3(NN / 128, HH), 256>>>();
    out_kernel <<<NN / 8, 256>>>(nodes, W1, b1, gamma, beta, out);
}

// round 11
// speedup vs baseline: 1.1283x; 1.1283x over previous
#include <cuda_runtime.h>
#include <cuda_bf16.h>
#include <cstdint>

// Problem constants
#define NN   4096
#define DD   128
#define HH   8
#define ALPHA 0.2f
#define LN_EPS 1e-5f
#define NJC  256           // 256 k-chunks of 16 j

typedef unsigned long long u64;

// ---------------- scratch (device globals; no allocation allowed) ----------------
// Wh^T in m16n8k16 B-fragment order, hi/lo interleaved per uint4, COALESCED:
// bf16 elem idx = ((((h*NJC + jc)*16 + dt)*32 + lane)*4 + comp)*2 + half
//   comp: 0=b0hi 1=b1hi 2=b0lo 3=b1lo ; b-reg = kk>>3 ; half = kk&1
//   lane = (d&7)*4 + ((kk&7)>>1) ; dt = d>>3 ; kk = j&15 ; jc = j>>4
__device__ __nv_bfloat16 g_whB[(size_t)HH * NJC * 16 * 32 * 8];   // 16.8 MB
__device__ float4   g_fq [HH * NN];                 // (f1, e^f1, e^{a f1}, 0)
__device__ float4   g_fk [HH * NN];                 // (f2, e^f2, e^{a f2}, 0)
__device__ float    g_cat[(size_t)NN * (HH * DD)];  // [n][h*128+d], 16 MB
__device__ unsigned g_adjbits[NN * (NN / 32)];      // bit-packed adj, 2 MB

// ---------------- helpers ----------------
__device__ __forceinline__ u64 pack2(float x, float y) {
    u64 r; asm("mov.b64 %0, {%1, %2};" : "=l"(r) : "f"(x), "f"(y)); return r;
}
__device__ __forceinline__ float2 unpack2(u64 v) {
    float2 r; asm("mov.b64 {%0, %1}, %2;" : "=f"(r.x), "=f"(r.y) : "l"(v)); return r;
}
__device__ __forceinline__ u64 ffma2(u64 a, u64 b, u64 c) {
    u64 d; asm("fma.rn.f32x2 %0, %1, %2, %3;" : "=l"(d) : "l"(a), "l"(b), "l"(c)); return d;
}
__device__ __forceinline__ float elu1(float x) { return x > 0.f ? x : expm1f(x); }
__device__ __forceinline__ uint32_t bf2_bits(__nv_bfloat162 v) {
    return *reinterpret_cast<uint32_t*>(&v);
}

// m16n8k16 bf16 mma: D(f32) += A(bf16,row) * B(bf16,col)
__device__ __forceinline__ void mma_bf16(float c[4],
                                         uint32_t a0, uint32_t a1, uint32_t a2, uint32_t a3,
                                         uint32_t b0, uint32_t b1) {
    asm volatile(
        "mma.sync.aligned.m16n8k16.row.col.f32.bf16.bf16.f32 "
        "{%0,%1,%2,%3}, {%4,%5,%6,%7}, {%8,%9}, {%0,%1,%2,%3};"
        : "+f"(c[0]), "+f"(c[1]), "+f"(c[2]), "+f"(c[3])
        : "r"(a0), "r"(a1), "r"(a2), "r"(a3), "r"(b0), "r"(b1));
}

// =================================================================
// Kernel 0: bit-pack adjacency. One warp per 32 columns.
// =================================================================
__global__ void pack_kernel(const int* __restrict__ adj) {
    int w    = blockIdx.x * 8 + (threadIdx.x >> 5);
    int lane = threadIdx.x & 31;
    int av = adj[(size_t)w * 32 + lane];
    unsigned m = __ballot_sync(0xffffffffu, av > 0);
    if (lane == 0) g_adjbits[w] = m;
}

// =================================================================
// Kernel 1: Wh = nodes @ W[h]; writes B-fragments + f1/f2 exp factors
// grid (64, 8), block 256. 64-node tile per CTA.
// =================================================================
__global__ void wh_kernel(const float* __restrict__ nodes, const float* __restrict__ W,
                          const float* __restrict__ a1, const float* __restrict__ a2) {
    __shared__ float ns[64][DD];
    const int h  = blockIdx.y;
    const int nb = blockIdx.x * 64;
    const int tid = threadIdx.x;

#pragma unroll
    for (int i = 0; i < 8; i++) {
        int f  = tid + 256 * i;
        int r  = f >> 5, c4 = f & 31;
        *(float4*)&ns[r][c4 * 4] = *(const float4*)&nodes[(size_t)(nb + r) * DD + c4 * 4];
    }
    __syncthreads();

    const int dg = tid & 31;   // lane: dims dg*4 .. dg*4+3
    const int ng = tid >> 5;   // warp: nodes ng*8 .. ng*8+7
    const float* Wb = W + (size_t)h * DD * DD;

    u64 acc[8][2];
#pragma unroll
    for (int n = 0; n < 8; n++) { acc[n][0] = 0ULL; acc[n][1] = 0ULL; }

#pragma unroll 4
    for (int k = 0; k < DD; k++) {
        float4 w4 = __ldg((const float4*)&Wb[k * DD + dg * 4]);
        u64 wxy = pack2(w4.x, w4.y);
        u64 wzw = pack2(w4.z, w4.w);
#pragma unroll
        for (int n = 0; n < 8; n++) {
            float s = ns[ng * 8 + n][k];
            u64 ss = pack2(s, s);
            acc[n][0] = ffma2(ss, wxy, acc[n][0]);
            acc[n][1] = ffma2(ss, wzw, acc[n][1]);
        }
    }

    float4 wh4[8];
#pragma unroll
    for (int n = 0; n < 8; n++) {
        float2 a = unpack2(acc[n][0]);
        float2 b = unpack2(acc[n][1]);
        wh4[n] = make_float4(a.x, a.y, b.x, b.y);
    }

    // ---- f1/f2 + exp factors ----
    float4 A1 = __ldg((const float4*)&a1[h * DD + dg * 4]);
    float4 A2 = __ldg((const float4*)&a2[h * DD + dg * 4]);
    float s1[8], s2[8];
#pragma unroll
    for (int n = 0; n < 8; n++) {
        s1[n] = wh4[n].x * A1.x + wh4[n].y * A1.y + wh4[n].z * A1.z + wh4[n].w * A1.w;
        s2[n] = wh4[n].x * A2.x + wh4[n].y * A2.y + wh4[n].z * A2.z + wh4[n].w * A2.w;
    }
#pragma unroll
    for (int o = 16; o > 0; o >>= 1) {
#pragma unroll
        for (int n = 0; n < 8; n++) {
            s1[n] += __shfl_xor_sync(0xffffffffu, s1[n], o);
            s2[n] += __shfl_xor_sync(0xffffffffu, s2[n], o);
        }
    }
    if (dg < 8) {
        float v1 = s1[0], v2 = s2[0];
#pragma unroll
        for (int n = 1; n < 8; n++)
            if (dg == n) { v1 = s1[n]; v2 = s2[n]; }
        int node = nb + ng * 8 + dg;
        g_fq[h * NN + node] = make_float4(v1, expf(v1), expf(ALPHA * v1), 0.f);
        g_fk[h * NN + node] = make_float4(v2, expf(v2), expf(ALPHA * v2), 0.f);
    }

    // ---- bf16 hi/lo B-fragment write (coalesced [jc][dt][lane] layout) ----
#pragma unroll
    for (int n = 0; n < 8; n++) {
        int j  = nb + ng * 8 + n;
        int jc = j >> 4, kk = j & 15;
        int comp = kk >> 3;          // which b-reg (hi slot; +2 for lo)
        int half = kk & 1;
        int lk   = (kk & 7) >> 1;
        size_t cb = ((size_t)(h * NJC + jc)) * 16;
        float vals[4] = {wh4[n].x, wh4[n].y, wh4[n].z, wh4[n].w};
#pragma unroll
        for (int q = 0; q < 4; q++) {
            int d = dg * 4 + q;
            int dt = d >> 3;
            int lane2 = (d & 7) * 4 + lk;
            size_t ei = (((cb + dt) * 32 + lane2) * 4 + comp) * 2 + half;
            float v = vals[q];
            __nv_bfloat16 hv = __float2bfloat16(v);
            g_whB[ei]     = hv;                                        // hi (comp)
            g_whB[ei + 4] = __float2bfloat16(v - __bfloat162float(hv)); // lo (comp+2)
        }
    }
}

// =================================================================
// Kernel 2: attention, operand-flipped (P = A operand).
// grid (64, 8): 64-query tile per CTA for head h. block 256.
// Warp (qg = wid&3, dh = wid>>2) owns q [qbase+qg*16, +16) x d [dh*64, +64).
// Per-jc __syncthreads keeps all warps on the same B chunk so L1
// dedupes the shared B-fragment stream (fixes the L2 drift bottleneck).
// All 8 B loads of a chunk are issued as one MLP-8 batch before 24 MMAs.
// =================================================================
__global__ void __launch_bounds__(256, 2) attn_kernel() {
    const int h     = blockIdx.y;
    const int qbase = blockIdx.x * 64;
    const int tid   = threadIdx.x;
    const int wid   = tid >> 5;
    const int lane  = tid & 31;
    const int r4  = lane >> 2;
    const int c42 = (lane & 3) * 2;
    const int qg  = wid & 3;       // q sub-tile
    const int dh  = wid >> 2;      // d half
    const int dtbase = dh * 8;

    const int q_lo = qbase + qg * 16 + r4;
    const int q_hi = q_lo + 8;

    const float4 fqlo = __ldg(&g_fq[h * NN + q_lo]);
    const float4 fqhi = __ldg(&g_fq[h * NN + q_hi]);

    float acc[8][4];
#pragma unroll
    for (int dt = 0; dt < 8; dt++)
#pragma unroll
        for (int i = 0; i < 4; i++) acc[dt][i] = 0.f;
    float llo = 0.f, lhi = 0.f;

    const float4*   fkb = g_fk + h * NN;
    const unsigned* abl = g_adjbits + (size_t)q_lo * (NN / 32);
    const unsigned* abh = g_adjbits + (size_t)q_hi * (NN / 32);
    const uint4*    Bb  = (const uint4*)g_whB + (size_t)h * NJC * 512 + dtbase * 32 + lane;

    unsigned wlo = 0, whi = 0;

#define PVAL(FQ, KV, BIT, W) \
    ({ float _t = (FQ).x + (KV).x; \
       float _p = (_t >= 0.f) ? (FQ).y * (KV).y : (FQ).z * (KV).z; \
       (((W) >> (BIT)) & 1u) ? _p : 0.f; })

#pragma unroll 1
    for (int jc = 0; jc < NJC; jc++) {
        __syncthreads();   // keep all warps on the same chunk: L1 reuse

        // issue all 8 B loads first (MLP=8, coalesced 512B each)
        const uint4* Bp = Bb + (size_t)jc * 512;
        uint4 b[8];
#pragma unroll
        for (int t = 0; t < 8; t++) b[t] = __ldg(&Bp[t * 32]);

        if ((jc & 1) == 0) {
            wlo = __ldg(&abl[jc >> 1]);
            whi = __ldg(&abh[jc >> 1]);
        }
        const int j0 = jc * 16 + c42;
        const int sh = ((jc & 1) << 4) + c42;

        float4 k0 = __ldg(&fkb[j0]);
        float4 k1 = __ldg(&fkb[j0 + 1]);
        float4 k2 = __ldg(&fkb[j0 + 8]);
        float4 k3 = __ldg(&fkb[j0 + 9]);

        // 8 score values in exact A-fragment positions
        float pl0 = PVAL(fqlo, k0, sh,     wlo);
        float pl1 = PVAL(fqlo, k1, sh + 1, wlo);
        float pl2 = PVAL(fqlo, k2, sh + 8, wlo);
        float pl3 = PVAL(fqlo, k3, sh + 9, wlo);
        float ph0 = PVAL(fqhi, k0, sh,     whi);
        float ph1 = PVAL(fqhi, k1, sh + 1, whi);
        float ph2 = PVAL(fqhi, k2, sh + 8, whi);
        float ph3 = PVAL(fqhi, k3, sh + 9, whi);

        llo += (pl0 + pl1) + (pl2 + pl3);
        lhi += (ph0 + ph1) + (ph2 + ph3);

        // hi/lo bf16 split, packed into A-frag regs
        __nv_bfloat162 hA0 = __floats2bfloat162_rn(pl0, pl1);
        __nv_bfloat162 hA1 = __floats2bfloat162_rn(ph0, ph1);
        __nv_bfloat162 hA2 = __floats2bfloat162_rn(pl2, pl3);
        __nv_bfloat162 hA3 = __floats2bfloat162_rn(ph2, ph3);
        __nv_bfloat162 lA0 = __floats2bfloat162_rn(pl0 - __low2float(hA0), pl1 - __high2float(hA0));
        __nv_bfloat162 lA1 = __floats2bfloat162_rn(ph0 - __low2float(hA1), ph1 - __high2float(hA1));
        __nv_bfloat162 lA2 = __floats2bfloat162_rn(pl2 - __low2float(hA2), pl3 - __high2float(hA2));
        __nv_bfloat162 lA3 = __floats2bfloat162_rn(ph2 - __low2float(hA3), ph3 - __high2float(hA3));
        uint32_t ah0 = bf2_bits(hA0), ah1 = bf2_bits(hA1), ah2 = bf2_bits(hA2), ah3 = bf2_bits(hA3);
        uint32_t al0 = bf2_bits(lA0), al1 = bf2_bits(lA1), al2 = bf2_bits(lA2), al3 = bf2_bits(lA3);

#pragma unroll
        for (int dt = 0; dt < 8; dt++) {
            mma_bf16(acc[dt], ah0, ah1, ah2, ah3, b[dt].x, b[dt].y);   // Phi * Whhi
            mma_bf16(acc[dt], al0, al1, al2, al3, b[dt].x, b[dt].y);   // Plo * Whhi
            mma_bf16(acc[dt], ah0, ah1, ah2, ah3, b[dt].z, b[dt].w);   // Phi * Whlo
        }
    }
#undef PVAL

    // softmax denominators: lanes sharing r4 (c4=0..3) cover all j
    llo += __shfl_xor_sync(0xffffffffu, llo, 1);
    llo += __shfl_xor_sync(0xffffffffu, llo, 2);
    lhi += __shfl_xor_sync(0xffffffffu, lhi, 1);
    lhi += __shfl_xor_sync(0xffffffffu, lhi, 2);
    const float inv_lo = 1.f / llo;
    const float inv_hi = 1.f / lhi;

    // normalize + ELU + write concat layout [q][h*128+d]
    float* rowl = g_cat + (size_t)q_lo * (HH * DD) + h * DD;
    float* rowh = g_cat + (size_t)q_hi * (HH * DD) + h * DD;
#pragma unroll
    for (int dt = 0; dt < 8; dt++) {
        int d0 = (dtbase + dt) * 8 + c42;
        *(float2*)&rowl[d0] = make_float2(elu1(acc[dt][0] * inv_lo), elu1(acc[dt][1] * inv_lo));
        *(float2*)&rowh[d0] = make_float2(elu1(acc[dt][2] * inv_hi), elu1(acc[dt][3] * inv_hi));
    }
}

// =================================================================
// Kernel 3: x = elu(cat @ W1 + b1); out = LN(nodes + x)
// grid 512 (8 nodes/CTA), block 256 (split-k halves)
// =================================================================
__global__ void out_kernel(const float* __restrict__ nodes,
                           const float* __restrict__ W1,
                           const float* __restrict__ b1,
                           const float* __restrict__ gamma,
                           const float* __restrict__ beta,
                           float* __restrict__ out) {
    __shared__ float cs[8][1024];    // 32 KB
    __shared__ float part[8][DD];    //  4 KB
    __shared__ float rbuf[8][DD];    //  4 KB

    const int nb  = blockIdx.x * 8;
    const int tid = threadIdx.x;
    const int kh  = tid >> 7;        // which k-half
    const int col = tid & 127;

#pragma unroll
    for (int i = 0; i < 8; i++) {
        int f = tid + 256 * i;
        int r = f >> 8, c4 = f & 255;
        *(float4*)&cs[r][c4 * 4] = *(const float4*)&g_cat[(size_t)(nb + r) * 1024 + c4 * 4];
    }
    __syncthreads();

    u64 acc2[8];
#pragma unroll
    for (int n = 0; n < 8; n++) acc2[n] = 0ULL;

    const int kbeg = kh * 512;
    for (int k = kbeg; k < kbeg + 512; k += 4) {
        float w0  = __ldg(&W1[(size_t)(k + 0) * DD + col]);
        float w1v = __ldg(&W1[(size_t)(k + 1) * DD + col]);
        float w2  = __ldg(&W1[(size_t)(k + 2) * DD + col]);
        float w3  = __ldg(&W1[(size_t)(k + 3) * DD + col]);
        u64 ww01 = pack2(w0, w1v);
        u64 ww23 = pack2(w2, w3);
#pragma unroll
        for (int n = 0; n < 8; n++) {
            float4 c = *(float4*)&cs[n][k];
            acc2[n] = ffma2(pack2(c.x, c.y), ww01, acc2[n]);
            acc2[n] = ffma2(pack2(c.z, c.w), ww23, acc2[n]);
        }
    }

    float acc[8];
#pragma unroll
    for (int n = 0; n < 8; n++) {
        float2 t = unpack2(acc2[n]);
        acc[n] = t.x + t.y;
    }

    if (kh == 1) {
#pragma unroll
        for (int n = 0; n < 8; n++) part[n][col] = acc[n];
    }
    __syncthreads();
    if (kh == 0) {
        float bb = __ldg(&b1[col]);
#pragma unroll
        for (int n = 0; n < 8; n++) {
            float x = elu1(acc[n] + part[n][col] + bb);
            rbuf[n][col] = nodes[(size_t)(nb + n) * DD + col] + x;
        }
    }
    __syncthreads();

    const int w    = tid >> 5;
    const int lane = tid & 31;
    float4 G = __ldg((const float4*)&gamma[lane * 4]);
    float4 B = __ldg((const float4*)&beta[lane * 4]);
    {
        float4 r = *(float4*)&rbuf[w][lane * 4];
        float s  = r.x + r.y + r.z + r.w;
        float ss = r.x * r.x + r.y * r.y + r.z * r.z + r.w * r.w;
#pragma unroll
        for (int o = 16; o > 0; o >>= 1) {
            s  += __shfl_xor_sync(0xffffffffu, s, o);
            ss += __shfl_xor_sync(0xffffffffu, ss, o);
        }
        float mu   = s * (1.f / DD);
        float var  = ss * (1.f / DD) - mu * mu;
        float rstd = rsqrtf(var + LN_EPS);
        float4 o4;
        o4.x = (r.x - mu) * rstd * G.x + B.x;
        o4.y = (r.y - mu) * rstd * G.y + B.y;
        o4.z = (r.z - mu) * rstd * G.z + B.z;
        o4.w = (r.w - mu) * rstd * G.w + B.w;
        *(float4*)&out[(size_t)(nb + w) * DD + lane * 4] = o4;
    }
}

// =================================================================
extern "C" void kernel_launch(void* const* d_in, const int* in_sizes, int n_in,
                              void* d_out, int out_size) {
    const float* nodes = (const float*)d_in[0];
    const int*   adj   = (const int*)  d_in[1];
    const float* W     = (const float*)d_in[2];
    const float* a1    = (const float*)d_in[3];
    const float* a2    = (const float*)d_in[4];
    const float* W1    = (const float*)d_in[5];
    const float* b1    = (const float*)d_in[6];
    const float* gamma = (const float*)d_in[7];
    const float* beta  = (const float*)d_in[8];
    float* out = (float*)d_out;

    pack_kernel<<<NN * (NN / 32) / 8, 256>>>(adj);
    wh_kernel  <<<dim3(NN / 64, HH), 256>>>(nodes, W, a1, a2);
    attn_kernel<<<dim3(NN / 64, HH), 256>>>();
    out_kernel <<<NN / 8, 256>>>(nodes, W1, b1, gamma, beta, out);
}

// round 13
// speedup vs baseline: 1.3639x; 1.2089x over previous
#include <cuda_runtime.h>
#include <cuda_bf16.h>
#include <cstdint>

// Problem constants
#define NN   4096
#define DD   128
#define HH   8
#define ALPHA 0.2f
#define LN_EPS 1e-5f
#define NJC32 128          // 128 chunks of 32 j (k32)

typedef unsigned long long u64;

// ---------------- scratch (device globals; no allocation allowed) ----------------
__device__ float    g_wh[(size_t)HH * NN * DD];     // fp32 Wh [h][n][d], 16 MB
// int8 B-fragment table for m16n8k32: per (h,jc,dt): 32 lanes x uint4
//   {x = w1 bytes k(4kq..+3), y = w1 k(16+4kq..), z = w2 k(4kq..), w = w2 k(16+..)}
__device__ uint4    g_whB[(size_t)HH * NJC32 * 16 * 32];   // 8.4 MB
__device__ float4   g_fq [HH * NN];                 // (f1, e^f1, e^{a f1}, 0)
__device__ float4   g_fk [HH * NN];                 // (f2, e^f2, e^{a f2}, 0)
__device__ float    g_cat[(size_t)NN * (HH * DD)];  // [n][h*128+d], 16 MB
__device__ unsigned g_adjbits[NN * (NN / 32)];      // bit-packed adj, 2 MB
__device__ unsigned g_wmaxbits[HH];                 // max|Wh| per head (float bits, >=0)
__device__ unsigned g_maxf2key[HH];                 // max f2 per head (order-encoded)

// ---------------- helpers ----------------
__device__ __forceinline__ u64 pack2(float x, float y) {
    u64 r; asm("mov.b64 %0, {%1, %2};" : "=l"(r) : "f"(x), "f"(y)); return r;
}
__device__ __forceinline__ float2 unpack2(u64 v) {
    float2 r; asm("mov.b64 {%0, %1}, %2;" : "=f"(r.x), "=f"(r.y) : "l"(v)); return r;
}
__device__ __forceinline__ u64 ffma2(u64 a, u64 b, u64 c) {
    u64 d; asm("fma.rn.f32x2 %0, %1, %2, %3;" : "=l"(d) : "l"(a), "l"(b), "l"(c)); return d;
}
__device__ __forceinline__ float elu1(float x) { return x > 0.f ? x : expm1f(x); }
// order-preserving float<->uint encoding (handles negatives)
__device__ __forceinline__ unsigned f2key(float f) {
    int ix = __float_as_int(f);
    return ix >= 0 ? ((unsigned)ix | 0x80000000u) : (unsigned)(~ix);
}
__device__ __forceinline__ float key2f(unsigned k) {
    int ix = (k & 0x80000000u) ? (int)(k & 0x7fffffffu) : ~(int)k;
    return __int_as_float(ix);
}

// m16n8k32 u8*s8 mma, s32 accumulate
__device__ __forceinline__ void mma_u8s8(int c[4],
                                         uint32_t a0, uint32_t a1, uint32_t a2, uint32_t a3,
                                         uint32_t b0, uint32_t b1) {
    asm volatile(
        "mma.sync.aligned.m16n8k32.row.col.s32.u8.s8.s32 "
        "{%0,%1,%2,%3}, {%4,%5,%6,%7}, {%8,%9}, {%0,%1,%2,%3};"
        : "+r"(c[0]), "+r"(c[1]), "+r"(c[2]), "+r"(c[3])
        : "r"(a0), "r"(a1), "r"(a2), "r"(a3), "r"(b0), "r"(b1));
}

#define PACKHI(v) __byte_perm(__byte_perm((v)[0], (v)[1], 0x0051), \
                              __byte_perm((v)[2], (v)[3], 0x0051), 0x5410)
#define PACKLO(v) __byte_perm(__byte_perm((v)[0], (v)[1], 0x0040), \
                              __byte_perm((v)[2], (v)[3], 0x0040), 0x5410)

// =================================================================
// Kernel 0: bit-pack adjacency. One warp per 32 columns.
// =================================================================
__global__ void pack_kernel(const int* __restrict__ adj) {
    int w    = blockIdx.x * 8 + (threadIdx.x >> 5);
    int lane = threadIdx.x & 31;
    int av = adj[(size_t)w * 32 + lane];
    unsigned m = __ballot_sync(0xffffffffu, av > 0);
    if (lane == 0) g_adjbits[w] = m;
}

// =================================================================
// Kernel 1: Wh = nodes @ W[h]; writes g_wh fp32, fq/fk, per-head maxes.
// grid (64, 8), block 256. 64-node tile per CTA.
// =================================================================
__global__ void wh_kernel(const float* __restrict__ nodes, const float* __restrict__ W,
                          const float* __restrict__ a1, const float* __restrict__ a2) {
    __shared__ float ns[64][DD];
    __shared__ float swm[8];
    __shared__ unsigned sf2[8];
    const int h  = blockIdx.y;
    const int nb = blockIdx.x * 64;
    const int tid = threadIdx.x;

#pragma unroll
    for (int i = 0; i < 8; i++) {
        int f  = tid + 256 * i;
        int r  = f >> 5, c4 = f & 31;
        *(float4*)&ns[r][c4 * 4] = *(const float4*)&nodes[(size_t)(nb + r) * DD + c4 * 4];
    }
    __syncthreads();

    const int dg = tid & 31;
    const int ng = tid >> 5;
    const float* Wb = W + (size_t)h * DD * DD;

    u64 acc[8][2];
#pragma unroll
    for (int n = 0; n < 8; n++) { acc[n][0] = 0ULL; acc[n][1] = 0ULL; }

#pragma unroll 4
    for (int k = 0; k < DD; k++) {
        float4 w4 = __ldg((const float4*)&Wb[k * DD + dg * 4]);
        u64 wxy = pack2(w4.x, w4.y);
        u64 wzw = pack2(w4.z, w4.w);
#pragma unroll
        for (int n = 0; n < 8; n++) {
            float s = ns[ng * 8 + n][k];
            u64 ss = pack2(s, s);
            acc[n][0] = ffma2(ss, wxy, acc[n][0]);
            acc[n][1] = ffma2(ss, wzw, acc[n][1]);
        }
    }

    float4 wh4[8];
    float wm = 0.f;
#pragma unroll
    for (int n = 0; n < 8; n++) {
        float2 a = unpack2(acc[n][0]);
        float2 b = unpack2(acc[n][1]);
        wh4[n] = make_float4(a.x, a.y, b.x, b.y);
        wm = fmaxf(wm, fmaxf(fmaxf(fabsf(a.x), fabsf(a.y)), fmaxf(fabsf(b.x), fabsf(b.y))));
        *(float4*)&g_wh[((size_t)h * NN + nb + ng * 8 + n) * DD + dg * 4] = wh4[n];
    }

    // ---- f1/f2 + exp factors ----
    float4 A1 = __ldg((const float4*)&a1[h * DD + dg * 4]);
    float4 A2 = __ldg((const float4*)&a2[h * DD + dg * 4]);
    float s1[8], s2[8];
#pragma unroll
    for (int n = 0; n < 8; n++) {
        s1[n] = wh4[n].x * A1.x + wh4[n].y * A1.y + wh4[n].z * A1.z + wh4[n].w * A1.w;
        s2[n] = wh4[n].x * A2.x + wh4[n].y * A2.y + wh4[n].z * A2.z + wh4[n].w * A2.w;
    }
#pragma unroll
    for (int o = 16; o > 0; o >>= 1) {
#pragma unroll
        for (int n = 0; n < 8; n++) {
            s1[n] += __shfl_xor_sync(0xffffffffu, s1[n], o);
            s2[n] += __shfl_xor_sync(0xffffffffu, s2[n], o);
        }
    }
    if (dg < 8) {
        float v1 = s1[0], v2 = s2[0];
#pragma unroll
        for (int n = 1; n < 8; n++)
            if (dg == n) { v1 = s1[n]; v2 = s2[n]; }
        int node = nb + ng * 8 + dg;
        g_fq[h * NN + node] = make_float4(v1, expf(v1), expf(ALPHA * v1), 0.f);
        g_fk[h * NN + node] = make_float4(v2, expf(v2), expf(ALPHA * v2), 0.f);
    }

    // ---- per-head maxes (CTA-reduced, then one atomic pair) ----
    float mf2 = s2[0];
#pragma unroll
    for (int n = 1; n < 8; n++) mf2 = fmaxf(mf2, s2[n]);
#pragma unroll
    for (int o = 16; o > 0; o >>= 1)
        wm = fmaxf(wm, __shfl_xor_sync(0xffffffffu, wm, o));
    if (dg == 0) { swm[ng] = wm; sf2[ng] = f2key(mf2); }
    __syncthreads();
    if (tid == 0) {
        float wmx = swm[0];
        unsigned kx = sf2[0];
#pragma unroll
        for (int i = 1; i < 8; i++) {
            wmx = fmaxf(wmx, swm[i]);
            kx  = max(kx, sf2[i]);
        }
        atomicMax(&g_wmaxbits[h], __float_as_uint(wmx));
        atomicMax(&g_maxf2key[h], kx);
    }
}

// =================================================================
// Kernel 1q: quantize Wh -> int8 double-word B fragments.
// grid (128 jc, 8 h), block 256.
// ws is UNPADDED so float4 staging stays 16B-aligned (R12 trap fix).
// =================================================================
__global__ void quant_kernel() {
    __shared__ float ws[32][DD];
    const int h  = blockIdx.y;
    const int jc = blockIdx.x;
    const int tid = threadIdx.x;

#pragma unroll
    for (int i = 0; i < 4; i++) {
        int f = tid + 256 * i;
        int r = f >> 5, c4 = f & 31;
        *(float4*)&ws[r][c4 * 4] =
            *(const float4*)&g_wh[((size_t)h * NN + jc * 32 + r) * DD + c4 * 4];
    }
    __syncthreads();

    const float inv_sw = 16383.f / __uint_as_float(g_wmaxbits[h]);

#pragma unroll
    for (int s = 0; s < 2; s++) {
        int slot = tid + 256 * s;
        int dt = slot >> 5, l2 = slot & 31;
        int d  = dt * 8 + (l2 >> 2);
        int kq = l2 & 3;
        uint32_t r1[2] = {0, 0}, r2[2] = {0, 0};
#pragma unroll
        for (int g = 0; g < 2; g++) {
#pragma unroll
            for (int i = 0; i < 4; i++) {
                int kk = g * 16 + 4 * kq + i;
                int wq = __float2int_rn(ws[kk][d] * inv_sw);
                int w1 = (wq + 128) >> 8;
                int w2 = wq - (w1 << 8);
                r1[g] |= (uint32_t)(w1 & 255) << (8 * i);
                r2[g] |= (uint32_t)(w2 & 255) << (8 * i);
            }
        }
        g_whB[((size_t)(h * NJC32 + jc) * 16 + dt) * 32 + l2] =
            make_uint4(r1[0], r1[1], r2[0], r2[1]);
    }
}

// =================================================================
// Kernel 2: attention via int8 double-word m16n8k32 mma (3 products).
// grid (64, 8): 64-query tile per CTA. block 256.
// Warp (qg = wid&3, dh = wid>>2) owns q 16 x d 64. k-chunk = 32 j.
// =================================================================
__global__ void __launch_bounds__(256, 2) attn_kernel() {
    const int h     = blockIdx.y;
    const int qbase = blockIdx.x * 64;
    const int tid   = threadIdx.x;
    const int wid   = tid >> 5;
    const int lane  = tid & 31;
    const int r4 = lane >> 2;
    const int c4 = lane & 3;
    const int qg = wid & 3;
    const int dh = wid >> 2;
    const int dtbase = dh * 8;

    const int q_lo = qbase + qg * 16 + r4;
    const int q_hi = q_lo + 8;

    const float4 fqlo = __ldg(&g_fq[h * NN + q_lo]);
    const float4 fqhi = __ldg(&g_fq[h * NN + q_hi]);

    // per-query quant scales: pmax is EXACT (p monotone in f2)
    const float maxf2 = key2f(g_maxf2key[h]);
    const float mx = expf(maxf2), mf = expf(ALPHA * maxf2);
    const float invlo = 32767.f / fmaxf(fqlo.y * mx, fqlo.z * mf);
    const float invhi = 32767.f / fmaxf(fqhi.y * mx, fqhi.z * mf);
    const float fxl = fqlo.x, eyl = fqlo.y * invlo, ezl = fqlo.z * invlo;
    const float fxh = fqhi.x, eyh = fqhi.y * invhi, ezh = fqhi.z * invhi;

    int a1acc[8][4], a2acc[8][4];
#pragma unroll
    for (int dt = 0; dt < 8; dt++)
#pragma unroll
        for (int i = 0; i < 4; i++) { a1acc[dt][i] = 0; a2acc[dt][i] = 0; }
    unsigned lsum_lo = 0, lsum_hi = 0;

    const float4*   fkb = g_fk + h * NN;
    const unsigned* abl = g_adjbits + (size_t)q_lo * NJC32;
    const unsigned* abh = g_adjbits + (size_t)q_hi * NJC32;
    const uint4*    Bb  = g_whB + (size_t)h * NJC32 * 512 + dtbase * 32 + lane;

#pragma unroll 1
    for (int jc = 0; jc < NJC32; jc++) {
        __syncthreads();   // keep warps on the same chunk for L1 reuse

        const uint4* Bp = Bb + (size_t)jc * 512;
        uint4 b[4];
#pragma unroll
        for (int t = 0; t < 4; t++) b[t] = __ldg(&Bp[t * 32]);

        const unsigned wlo = __ldg(&abl[jc]);
        const unsigned whi = __ldg(&abh[jc]);
        const float4* Kp = fkb + jc * 32;

        uint32_t ap1[4], ap2[4];
#pragma unroll
        for (int g = 0; g < 2; g++) {
            uint32_t vl[4], vh[4];
#pragma unroll
            for (int i = 0; i < 4; i++) {
                int kk = g * 16 + 4 * c4 + i;
                float4 K = __ldg(&Kp[kk]);
                float tl = fxl + K.x;
                float pl = (tl >= 0.f) ? eyl * K.y : ezl * K.z;
                pl = ((wlo >> kk) & 1u) ? pl : 0.f;
                vl[i] = __float2uint_rn(pl);
                float th = fxh + K.x;
                float ph = (th >= 0.f) ? eyh * K.y : ezh * K.z;
                ph = ((whi >> kk) & 1u) ? ph : 0.f;
                vh[i] = __float2uint_rn(ph);
            }
            lsum_lo += (vl[0] + vl[1]) + (vl[2] + vl[3]);
            lsum_hi += (vh[0] + vh[1]) + (vh[2] + vh[3]);
            ap1[g * 2 + 0] = PACKHI(vl); ap2[g * 2 + 0] = PACKLO(vl);
            ap1[g * 2 + 1] = PACKHI(vh); ap2[g * 2 + 1] = PACKLO(vh);
        }

        // batch 1 (dt 0..3): sweeps, dependency distance 4
#pragma unroll
        for (int t = 0; t < 4; t++) mma_u8s8(a1acc[t], ap1[0], ap1[1], ap1[2], ap1[3], b[t].x, b[t].y);
#pragma unroll
        for (int t = 0; t < 4; t++) mma_u8s8(a2acc[t], ap2[0], ap2[1], ap2[2], ap2[3], b[t].x, b[t].y);
#pragma unroll
        for (int t = 0; t < 4; t++) mma_u8s8(a2acc[t], ap1[0], ap1[1], ap1[2], ap1[3], b[t].z, b[t].w);

        // batch 2 (dt 4..7)
#pragma unroll
        for (int t = 0; t < 4; t++) b[t] = __ldg(&Bp[(t + 4) * 32]);
#pragma unroll
        for (int t = 0; t < 4; t++) mma_u8s8(a1acc[t + 4], ap1[0], ap1[1], ap1[2], ap1[3], b[t].x, b[t].y);
#pragma unroll
        for (int t = 0; t < 4; t++) mma_u8s8(a2acc[t + 4], ap2[0], ap2[1], ap2[2], ap2[3], b[t].x, b[t].y);
#pragma unroll
        for (int t = 0; t < 4; t++) mma_u8s8(a2acc[t + 4], ap1[0], ap1[1], ap1[2], ap1[3], b[t].z, b[t].w);
    }

    // softmax denominators: lanes sharing r4 (c4 0..3) cover all j
    lsum_lo += __shfl_xor_sync(0xffffffffu, lsum_lo, 1);
    lsum_lo += __shfl_xor_sync(0xffffffffu, lsum_lo, 2);
    lsum_hi += __shfl_xor_sync(0xffffffffu, lsum_hi, 1);
    lsum_hi += __shfl_xor_sync(0xffffffffu, lsum_hi, 2);
    const float sw = __uint_as_float(g_wmaxbits[h]) / 16383.f;
    const float scl_lo = sw / fmaxf((float)lsum_lo, 1.f);
    const float scl_hi = sw / fmaxf((float)lsum_hi, 1.f);

    // combine: h = (A1*65536 + A2*256) * sw / sum(p~)
    float* rowl = g_cat + (size_t)q_lo * (HH * DD) + h * DD;
    float* rowh = g_cat + (size_t)q_hi * (HH * DD) + h * DD;
#pragma unroll
    for (int dt = 0; dt < 8; dt++) {
        int d0 = (dtbase + dt) * 8 + c4 * 2;
        float v0 = (65536.f * (float)a1acc[dt][0] + 256.f * (float)a2acc[dt][0]) * scl_lo;
        float v1 = (65536.f * (float)a1acc[dt][1] + 256.f * (float)a2acc[dt][1]) * scl_lo;
        float v2 = (65536.f * (float)a1acc[dt][2] + 256.f * (float)a2acc[dt][2]) * scl_hi;
        float v3 = (65536.f * (float)a1acc[dt][3] + 256.f * (float)a2acc[dt][3]) * scl_hi;
        *(float2*)&rowl[d0] = make_float2(elu1(v0), elu1(v1));
        *(float2*)&rowh[d0] = make_float2(elu1(v2), elu1(v3));
    }
}

// =================================================================
// Kernel 3: x = elu(cat @ W1 + b1); out = LN(nodes + x)
// grid 512 (8 nodes/CTA), block 256 (split-k halves)
// =================================================================
__global__ void out_kernel(const float* __restrict__ nodes,
                           const float* __restrict__ W1,
                           const float* __restrict__ b1,
                           const float* __restrict__ gamma,
                           const float* __restrict__ beta,
                           float* __restrict__ out) {
    __shared__ float cs[8][1024];
    __shared__ float part[8][DD];
    __shared__ float rbuf[8][DD];

    const int nb  = blockIdx.x * 8;
    const int tid = threadIdx.x;
    const int kh  = tid >> 7;
    const int col = tid & 127;

#pragma unroll
    for (int i = 0; i < 8; i++) {
        int f = tid + 256 * i;
        int r = f >> 8, c4 = f & 255;
        *(float4*)&cs[r][c4 * 4] = *(const float4*)&g_cat[(size_t)(nb + r) * 1024 + c4 * 4];
    }
    __syncthreads();

    u64 acc2[8];
#pragma unroll
    for (int n = 0; n < 8; n++) acc2[n] = 0ULL;

    const int kbeg = kh * 512;
    for (int k = kbeg; k < kbeg + 512; k += 4) {
        float w0  = __ldg(&W1[(size_t)(k + 0) * DD + col]);
        float w1v = __ldg(&W1[(size_t)(k + 1) * DD + col]);
        float w2  = __ldg(&W1[(size_t)(k + 2) * DD + col]);
        float w3  = __ldg(&W1[(size_t)(k + 3) * DD + col]);
        u64 ww01 = pack2(w0, w1v);
        u64 ww23 = pack2(w2, w3);
#pragma unroll
        for (int n = 0; n < 8; n++) {
            float4 c = *(float4*)&cs[n][k];
            acc2[n] = ffma2(pack2(c.x, c.y), ww01, acc2[n]);
            acc2[n] = ffma2(pack2(c.z, c.w), ww23, acc2[n]);
        }
    }

    float acc[8];
#pragma unroll
    for (int n = 0; n < 8; n++) {
        float2 t = unpack2(acc2[n]);
        acc[n] = t.x + t.y;
    }

    if (kh == 1) {
#pragma unroll
        for (int n = 0; n < 8; n++) part[n][col] = acc[n];
    }
    __syncthreads();
    if (kh == 0) {
        float bb = __ldg(&b1[col]);
#pragma unroll
        for (int n = 0; n < 8; n++) {
            float x = elu1(acc[n] + part[n][col] + bb);
            rbuf[n][col] = nodes[(size_t)(nb + n) * DD + col] + x;
        }
    }
    __syncthreads();

    const int w    = tid >> 5;
    const int lane = tid & 31;
    float4 G = __ldg((const float4*)&gamma[lane * 4]);
    float4 B = __ldg((const float4*)&beta[lane * 4]);
    {
        float4 r = *(float4*)&rbuf[w][lane * 4];
        float s  = r.x + r.y + r.z + r.w;
        float ss = r.x * r.x + r.y * r.y + r.z * r.z + r.w * r.w;
#pragma unroll
        for (int o = 16; o > 0; o >>= 1) {
            s  += __shfl_xor_sync(0xffffffffu, s, o);
            ss += __shfl_xor_sync(0xffffffffu, ss, o);
        }
        float mu   = s * (1.f / DD);
        float var  = ss * (1.f / DD) - mu * mu;
        float rstd = rsqrtf(var + LN_EPS);
        float4 o4;
        o4.x = (r.x - mu) * rstd * G.x + B.x;
        o4.y = (r.y - mu) * rstd * G.y + B.y;
        o4.z = (r.z - mu) * rstd * G.z + B.z;
        o4.w = (r.w - mu) * rstd * G.w + B.w;
        *(float4*)&out[(size_t)(nb + w) * DD + lane * 4] = o4;
    }
}

// =================================================================
extern "C" void kernel_launch(void* const* d_in, const int* in_sizes, int n_in,
                              void* d_out, int out_size) {
    const float* nodes = (const float*)d_in[0];
    const int*   adj   = (const int*)  d_in[1];
    const float* W     = (const float*)d_in[2];
    const float* a1    = (const float*)d_in[3];
    const float* a2    = (const float*)d_in[4];
    const float* W1    = (const float*)d_in[5];
    const float* b1    = (const float*)d_in[6];
    const float* gamma = (const float*)d_in[7];
    const float* beta  = (const float*)d_in[8];
    float* out = (float*)d_out;

    pack_kernel <<<NN * (NN / 32) / 8, 256>>>(adj);
    wh_kernel   <<<dim3(NN / 64, HH), 256>>>(nodes, W, a1, a2);
    quant_kernel<<<dim3(NJC32, HH), 256>>>();
    attn_kernel <<<dim3(NN / 64, HH), 256>>>();
    out_kernel  <<<NN / 8, 256>>>(nodes, W1, b1, gamma, beta, out);
}